// round 14
// baseline (speedup 1.0000x reference)
#include <cuda_runtime.h>
#include <cstdint>

// Problem constants
#define OUT_N 11008
#define IN_K  4096
#define GS    128
#define NG    32          // groups per row
#define M_TOK 8

// Tiling
#define BLOCK            256
#define WARPS            8
#define T_ROWS           2                      // output rows per warp
#define ROWS_PER_BLOCK   (WARPS * T_ROWS)       // 16 -> grid 688
#define WSLOTS           4                      // per-warp weight ring slots
#define WDEPTH           3                      // weight stages in flight
#define XGPC             4                      // groups per x chunk (512 k)
#define NXCHUNK          (NG / XGPC)            // 8 chunks

typedef unsigned long long u64;

// ---- packed f32x2 helpers (Blackwell FFMA2 path; ptxas won't emit from C++) ----
__device__ __forceinline__ u64 pkf(float lo, float hi) {
    u64 r; asm("mov.b64 %0, {%1, %2};" : "=l"(r) : "f"(lo), "f"(hi)); return r;
}
__device__ __forceinline__ u64 pki(unsigned lo, unsigned hi) {
    u64 r; asm("mov.b64 %0, {%1, %2};" : "=l"(r) : "r"(lo), "r"(hi)); return r;
}
__device__ __forceinline__ u64 add2(u64 a, u64 b) {
    u64 r; asm("add.rn.f32x2 %0, %1, %2;" : "=l"(r) : "l"(a), "l"(b)); return r;
}
__device__ __forceinline__ u64 mul2(u64 a, u64 b) {
    u64 r; asm("mul.rn.f32x2 %0, %1, %2;" : "=l"(r) : "l"(a), "l"(b)); return r;
}
__device__ __forceinline__ u64 fma2(u64 a, u64 b, u64 c) {
    u64 r; asm("fma.rn.f32x2 %0, %1, %2, %3;" : "=l"(r) : "l"(a), "l"(b), "l"(c)); return r;
}
__device__ __forceinline__ float2 upk(u64 a) {
    float lo, hi; asm("mov.b64 {%0, %1}, %2;" : "=f"(lo), "=f"(hi) : "l"(a));
    return make_float2(lo, hi);
}

// ---- cp.async (LDGSTS) helpers ----
__device__ __forceinline__ void cpa16(unsigned smem_addr, const void* gptr) {
    asm volatile("cp.async.cg.shared.global [%0], [%1], 16;"
                 :: "r"(smem_addr), "l"(gptr) : "memory");
}
__device__ __forceinline__ void cpa_commit() {
    asm volatile("cp.async.commit_group;" ::: "memory");
}
__device__ __forceinline__ void cpa_wait2() {
    asm volatile("cp.async.wait_group 2;" ::: "memory");   // WDEPTH-1
}

// weight-stage fill: 2 self-chunks per lane, one commit group. wbase is this
// thread's byte address of wr slot-0 entry; slot stride = 1 KB.
__device__ __forceinline__ void wfill(unsigned wbase, const int4* q0,
                                      const int4* q1, int g) {
    const unsigned sa = wbase + (unsigned)(g & (WSLOTS - 1)) * 1024u;
    cpa16(sa,       q0 + g * 32);
    cpa16(sa + 512, q1 + g * 32);
    cpa_commit();
}

// Barrier-light pipeline:
//  - weights: per-warp private cp.async ring; each lane reads ONLY the chunks it
//    wrote itself, so per-thread wait_group is sufficient -> NO barrier.
//  - x: 512-k chunks, double buffered, loaded one chunk ahead via LDG->STS;
//    __syncthreads only at chunk boundaries (8 barriers total, not 32).
__global__ void __launch_bounds__(BLOCK, 3)
qlinear_pergrp_kernel(const float* __restrict__ x,
                      const int*   __restrict__ qw,
                      const int*   __restrict__ qz,
                      const float* __restrict__ sc,
                      float*       __restrict__ out)
{
    // x: [buf][group-in-chunk][token][lane] float4
    __shared__ float4 xb[2][XGPC][M_TOK][32];                       // 32 KB
    // weight rings: [warp][slot][row][lane] int4, flattened
    __shared__ int4 wr[WARPS * WSLOTS * T_ROWS * 32];               // 32 KB

    const int tid  = threadIdx.x;
    const int warp = tid >> 5;
    const int lane = tid & 31;
    const int row0 = blockIdx.x * ROWS_PER_BLOCK + warp * T_ROWS;

    const float4* xg = (const float4*)x;               // x[m][k/4]
    const float* scp = sc + (size_t)row0 * NG;
    const int*   qzp = qz + (size_t)row0 * NG;

    // weight source: lane-self chunks (lane L fills and reads its own int4)
    const int4* q0 = (const int4*)(qw + (size_t)row0 * IN_K) + lane;
    const int4* q1 = q0 + (IN_K / 4);

    // this thread's smem addresses in its warp's ring
    // layout: warp*4096 + slot*1024 + row*512 + lane*16 bytes
    const unsigned wr_base =
        (unsigned)__cvta_generic_to_shared(wr) + (unsigned)(warp * 4096 + lane * 16);
    const int4* wr_rd0 = &wr[warp * 256 + lane];            // slot s: + s*64
    const int4* wr_rd1 = wr_rd0 + 32;

    // ---- prologue: x chunk 0 + weight stages 0..2 ----
    {
        const int m0 = tid >> 7, i0 = tid & 127;            // 2 f4 per thread pass
#pragma unroll
        for (int j = 0; j < 4; j++) {
            const int idx = j * BLOCK + tid;
            const int m = idx >> 7, i = idx & 127;
            xb[0][i >> 5][m][i & 31] = xg[m * (IN_K / 4) + i];
        }
        (void)m0; (void)i0;
    }
    wfill(wr_base, q0, q1, 0);
    wfill(wr_base, q0, q1, 1);
    wfill(wr_base, q0, q1, 2);
    __syncthreads();                                   // x chunk 0 visible

    u64 acc[T_ROWS][M_TOK];
#pragma unroll
    for (int r = 0; r < T_ROWS; r++)
#pragma unroll
        for (int m = 0; m < M_TOK; m++) acc[r][m] = 0ULL;

    for (int c = 0; c < NXCHUNK; c++) {
        // issue next x chunk now (buffer last read in chunk c-1; all its readers
        // passed the previous boundary barrier, so overwrite is safe)
        if (c + 1 < NXCHUNK) {
            const int nb = (c + 1) & 1;
#pragma unroll
            for (int j = 0; j < 4; j++) {
                const int idx = j * BLOCK + tid;
                const int m = idx >> 7, i = idx & 127;
                xb[nb][i >> 5][m][i & 31] = xg[m * (IN_K / 4) + (c + 1) * 128 + i];
            }
        }
        const int buf = c & 1;

#pragma unroll
        for (int jj = 0; jj < XGPC; jj++) {
            const int g = c * XGPC + jj;

            cpa_wait2();                               // own weight chunks of g landed

            // per-group constants (warp-uniform, L1-hit)
            const float s0 = __ldg(scp + g);
            const float s1 = __ldg(scp + NG + g);
            const int   z0 = __ldg(qzp + g);
            const int   z1 = __ldg(qzp + NG + g);
            const float nz0 = __int_as_float((z0 | 0x4B000000) ^ 0x80000000);
            const float nz1 = __int_as_float((z1 | 0x4B000000) ^ 0x80000000);
            const u64 ss0 = pkf(s0, s0),  zz0 = pkf(nz0, nz0);
            const u64 ss1 = pkf(s1, s1),  zz1 = pkf(nz1, nz1);

            // self-written weight chunks (no barrier needed)
            const int so = (g & (WSLOTS - 1)) * 64;
            const int4 w0 = wr_rd0[so];
            const int4 w1 = wr_rd1[so];

            // dequant k-packed f32x2:
            // as_float(q|0x4B000000)==2^23+q ; +(-(2^23+z)) is Sterbenz-exact
            const u64 a01 = mul2(add2(pki((unsigned)w0.x | 0x4B000000u,
                                          (unsigned)w0.y | 0x4B000000u), zz0), ss0);
            const u64 a23 = mul2(add2(pki((unsigned)w0.z | 0x4B000000u,
                                          (unsigned)w0.w | 0x4B000000u), zz0), ss0);
            const u64 b01 = mul2(add2(pki((unsigned)w1.x | 0x4B000000u,
                                          (unsigned)w1.y | 0x4B000000u), zz1), ss1);
            const u64 b23 = mul2(add2(pki((unsigned)w1.z | 0x4B000000u,
                                          (unsigned)w1.w | 0x4B000000u), zz1), ss1);

#pragma unroll
            for (int m = 0; m < M_TOK; m++) {
                const float4 xv = xb[buf][jj][m][lane];    // LDS.128, conflict-free
                const u64 x01 = pkf(xv.x, xv.y);
                const u64 x23 = pkf(xv.z, xv.w);
                acc[0][m] = fma2(a01, x01, acc[0][m]);
                acc[0][m] = fma2(a23, x23, acc[0][m]);
                acc[1][m] = fma2(b01, x01, acc[1][m]);
                acc[1][m] = fma2(b23, x23, acc[1][m]);
            }

            // refill own ring (slot (g+3)&3: this thread finished reading it at g-1)
            if (g + WDEPTH < NG) wfill(wr_base, q0, q1, g + WDEPTH);
            else                 cpa_commit();         // keep per-thread counts aligned
        }

        __syncthreads();   // chunk boundary: next x buffer visible, current released
    }

    // ---- fold f32x2 halves, then intra-warp reduction over the k-split ----
#pragma unroll
    for (int r = 0; r < T_ROWS; r++)
#pragma unroll
        for (int m = 0; m < M_TOK; m++) {
            const float2 v = upk(acc[r][m]);
            float s = v.x + v.y;
#pragma unroll
            for (int off = 16; off > 0; off >>= 1)
                s += __shfl_xor_sync(0xffffffffu, s, off);
            if (lane == 0)
                out[m * OUT_N + (row0 + r)] = s;
        }
}

extern "C" void kernel_launch(void* const* d_in, const int* in_sizes, int n_in,
                              void* d_out, int out_size)
{
    const float* x  = (const float*)d_in[0];   // [8, 4096] f32
    const int*   qw = (const int*)  d_in[1];   // [11008, 4096] int32 in [0,15]
    const int*   qz = (const int*)  d_in[2];   // [11008, 32] int32
    const float* sc = (const float*)d_in[3];   // [11008, 32] f32
    float* out = (float*)d_out;                // [8, 11008] f32

    const int grid = OUT_N / ROWS_PER_BLOCK;   // 688
    qlinear_pergrp_kernel<<<grid, BLOCK>>>(x, qw, qz, sc, out);
}